// round 1
// baseline (speedup 1.0000x reference)
#include <cuda_runtime.h>

// Problem constants (fixed shapes): B=4, S=1024, D=1024, F=4096, E=8, TOPK=2
#define NTOK 4096
#define DIM  1024
#define FDIM 4096
#define NEXP 8

#define BM 128
#define BN 128
#define BK 16

// ---------------- scratch (device globals; no allocation allowed) -------------
__device__ int   g_count[NEXP];                       // tokens per expert
__device__ int   g_list[NEXP * NTOK];                 // token ids per expert
__device__ float g_prob[NEXP * NTOK];                 // router prob per entry
__device__ int   g_top_idx[NTOK * 2];                 // per-token top-2 experts
__device__ float g_top_p[NTOK * 2];                   // per-token top-2 probs
__device__ __align__(256) float g_h[(size_t)NTOK * FDIM];  // combined hidden [N,F] (64 MB)

// ---------------- init: zero h and counts ------------------------------------
__global__ void init_kernel() {
    size_t i = (size_t)blockIdx.x * blockDim.x + threadIdx.x;
    size_t total4 = (size_t)NTOK * FDIM / 4;
    float4 z = make_float4(0.f, 0.f, 0.f, 0.f);
    float4* h4 = reinterpret_cast<float4*>(g_h);
    for (size_t idx = i; idx < total4; idx += (size_t)gridDim.x * blockDim.x)
        h4[idx] = z;
    if (i < NEXP) g_count[i] = 0;
}

// ---------------- router: logits -> softmax -> top2 -> expert lists ----------
__global__ void router_kernel(const float* __restrict__ x,
                              const float* __restrict__ Wr,
                              const float* __restrict__ br) {
    int n = blockIdx.x;
    int t = threadIdx.x;  // 128 threads
    const float* xr = x + (size_t)n * DIM;
    float acc[NEXP];
#pragma unroll
    for (int e = 0; e < NEXP; e++) acc[e] = 0.f;
    for (int d = t; d < DIM; d += 128) {
        float xv = xr[d];
        const float* w = Wr + (size_t)d * NEXP;
#pragma unroll
        for (int e = 0; e < NEXP; e++) acc[e] += xv * w[e];
    }
#pragma unroll
    for (int e = 0; e < NEXP; e++) {
#pragma unroll
        for (int off = 16; off > 0; off >>= 1)
            acc[e] += __shfl_down_sync(0xffffffffu, acc[e], off);
    }
    __shared__ float part[4][NEXP];
    int warp = t >> 5, lane = t & 31;
    if (lane == 0) {
#pragma unroll
        for (int e = 0; e < NEXP; e++) part[warp][e] = acc[e];
    }
    __syncthreads();
    if (t == 0) {
        float logit[NEXP];
        float mx = -1e30f;
#pragma unroll
        for (int e = 0; e < NEXP; e++) {
            logit[e] = part[0][e] + part[1][e] + part[2][e] + part[3][e] + br[e];
            mx = fmaxf(mx, logit[e]);
        }
        float p[NEXP], sum = 0.f;
#pragma unroll
        for (int e = 0; e < NEXP; e++) { p[e] = expf(logit[e] - mx); sum += p[e]; }
        float inv = 1.f / sum;
#pragma unroll
        for (int e = 0; e < NEXP; e++) p[e] *= inv;
        // top-2, ties broken toward lower index (matches lax.top_k)
        int e1 = 0;
#pragma unroll
        for (int e = 1; e < NEXP; e++) if (p[e] > p[e1]) e1 = e;
        int e2 = (e1 == 0) ? 1 : 0;
#pragma unroll
        for (int e = 0; e < NEXP; e++) {
            if (e == e1 || e == e2) continue;
            if (p[e] > p[e2]) e2 = e;
        }
        g_top_idx[2 * n] = e1;  g_top_p[2 * n] = p[e1];
        g_top_idx[2 * n + 1] = e2;  g_top_p[2 * n + 1] = p[e2];
        int pos1 = atomicAdd(&g_count[e1], 1);
        g_list[e1 * NTOK + pos1] = n;
        g_prob[e1 * NTOK + pos1] = p[e1];
        int pos2 = atomicAdd(&g_count[e2], 1);
        g_list[e2 * NTOK + pos2] = n;
        g_prob[e2 * NTOK + pos2] = p[e2];
    }
}

// ---------------- y init: y[n,:] = p1*b_out[e1,:] + p2*b_out[e2,:] -----------
__global__ void yinit_kernel(const float* __restrict__ b_out, float* __restrict__ y) {
    int i = blockIdx.x * blockDim.x + threadIdx.x;
    if (i >= NTOK * DIM) return;
    int n = i >> 10;      // / DIM
    int d = i & (DIM - 1);
    int e1 = g_top_idx[2 * n], e2 = g_top_idx[2 * n + 1];
    float p1 = g_top_p[2 * n], p2 = g_top_p[2 * n + 1];
    y[i] = p1 * b_out[e1 * DIM + d] + p2 * b_out[e2 * DIM + d];
}

// ---------------- GEMM1: h[tok,:] += relu(gather(x) @ W_in[e] + b_in[e]) -----
__global__ __launch_bounds__(256, 2)
void gemm1_kernel(const float* __restrict__ x,
                  const float* __restrict__ W_in,
                  const float* __restrict__ b_in) {
    int e = blockIdx.z;
    int cnt = g_count[e];
    int m0 = blockIdx.y * BM;
    if (m0 >= cnt) return;
    int n0 = blockIdx.x * BN;

    __shared__ float As[BK][BM];
    __shared__ float Bs[BK][BN];
    __shared__ int   stok[BM];

    int tid = threadIdx.x;
    for (int i = tid; i < BM; i += 256) {
        int r = m0 + i;
        stok[i] = (r < cnt) ? g_list[e * NTOK + r] : -1;
    }
    __syncthreads();

    float acc[8][8];
#pragma unroll
    for (int i = 0; i < 8; i++)
#pragma unroll
        for (int j = 0; j < 8; j++) acc[i][j] = 0.f;

    int trow = tid >> 4;  // 0..15
    int tcol = tid & 15;  // 0..15
    const float* Bbase = W_in + (size_t)e * DIM * FDIM + n0;

    for (int k0 = 0; k0 < DIM; k0 += BK) {
        // A tile (gathered token rows), stored transposed As[k][m]
#pragma unroll
        for (int u = 0; u < 2; u++) {
            int idx = tid + u * 256;          // float4 index, 0..511
            int row = idx >> 2;
            int kq = (idx & 3) << 2;
            int tok = stok[row];
            float4 v = make_float4(0.f, 0.f, 0.f, 0.f);
            if (tok >= 0)
                v = *reinterpret_cast<const float4*>(x + (size_t)tok * DIM + k0 + kq);
            As[kq + 0][row] = v.x;
            As[kq + 1][row] = v.y;
            As[kq + 2][row] = v.z;
            As[kq + 3][row] = v.w;
        }
        // B tile (W_in rows k0..k0+15, cols n0..n0+127)
#pragma unroll
        for (int u = 0; u < 2; u++) {
            int idx = tid + u * 256;
            int kr = idx >> 5;
            int c4 = (idx & 31) << 2;
            *reinterpret_cast<float4*>(&Bs[kr][c4]) =
                *reinterpret_cast<const float4*>(Bbase + (size_t)(k0 + kr) * FDIM + c4);
        }
        __syncthreads();
#pragma unroll
        for (int kk = 0; kk < BK; kk++) {
            float4 ma = *reinterpret_cast<const float4*>(&As[kk][trow * 8]);
            float4 mb = *reinterpret_cast<const float4*>(&As[kk][trow * 8 + 4]);
            float4 na = *reinterpret_cast<const float4*>(&Bs[kk][tcol * 8]);
            float4 nb = *reinterpret_cast<const float4*>(&Bs[kk][tcol * 8 + 4]);
            float rm[8] = {ma.x, ma.y, ma.z, ma.w, mb.x, mb.y, mb.z, mb.w};
            float rn[8] = {na.x, na.y, na.z, na.w, nb.x, nb.y, nb.z, nb.w};
#pragma unroll
            for (int i = 0; i < 8; i++)
#pragma unroll
                for (int j = 0; j < 8; j++) acc[i][j] += rm[i] * rn[j];
        }
        __syncthreads();
    }

    const float* brow = b_in + (size_t)e * FDIM + n0 + tcol * 8;
    float bias[8];
#pragma unroll
    for (int j = 0; j < 8; j++) bias[j] = brow[j];
#pragma unroll
    for (int i = 0; i < 8; i++) {
        int r = trow * 8 + i;
        int tok = stok[r];
        if (tok < 0) continue;
        float* hr = g_h + (size_t)tok * FDIM + n0 + tcol * 8;
#pragma unroll
        for (int j = 0; j < 8; j++) {
            float c = fmaxf(acc[i][j] + bias[j], 0.f);
            atomicAdd(hr + j, c);
        }
    }
}

// ---------------- GEMM2: y[tok,:] += p * (gather(h) @ W_out[e]) --------------
__global__ __launch_bounds__(256, 2)
void gemm2_kernel(const float* __restrict__ W_out, float* __restrict__ y) {
    int e = blockIdx.z;
    int cnt = g_count[e];
    int m0 = blockIdx.y * BM;
    if (m0 >= cnt) return;
    int n0 = blockIdx.x * BN;

    __shared__ float As[BK][BM];
    __shared__ float Bs[BK][BN];
    __shared__ int   stok[BM];
    __shared__ float sprob[BM];

    int tid = threadIdx.x;
    for (int i = tid; i < BM; i += 256) {
        int r = m0 + i;
        if (r < cnt) {
            stok[i] = g_list[e * NTOK + r];
            sprob[i] = g_prob[e * NTOK + r];
        } else {
            stok[i] = -1;
            sprob[i] = 0.f;
        }
    }
    __syncthreads();

    float acc[8][8];
#pragma unroll
    for (int i = 0; i < 8; i++)
#pragma unroll
        for (int j = 0; j < 8; j++) acc[i][j] = 0.f;

    int trow = tid >> 4;
    int tcol = tid & 15;
    const float* Bbase = W_out + (size_t)e * FDIM * DIM + n0;

    for (int k0 = 0; k0 < FDIM; k0 += BK) {
#pragma unroll
        for (int u = 0; u < 2; u++) {
            int idx = tid + u * 256;
            int row = idx >> 2;
            int kq = (idx & 3) << 2;
            int tok = stok[row];
            float4 v = make_float4(0.f, 0.f, 0.f, 0.f);
            if (tok >= 0)
                v = *reinterpret_cast<const float4*>(g_h + (size_t)tok * FDIM + k0 + kq);
            As[kq + 0][row] = v.x;
            As[kq + 1][row] = v.y;
            As[kq + 2][row] = v.z;
            As[kq + 3][row] = v.w;
        }
#pragma unroll
        for (int u = 0; u < 2; u++) {
            int idx = tid + u * 256;
            int kr = idx >> 5;
            int c4 = (idx & 31) << 2;
            *reinterpret_cast<float4*>(&Bs[kr][c4]) =
                *reinterpret_cast<const float4*>(Bbase + (size_t)(k0 + kr) * DIM + c4);
        }
        __syncthreads();
#pragma unroll
        for (int kk = 0; kk < BK; kk++) {
            float4 ma = *reinterpret_cast<const float4*>(&As[kk][trow * 8]);
            float4 mb = *reinterpret_cast<const float4*>(&As[kk][trow * 8 + 4]);
            float4 na = *reinterpret_cast<const float4*>(&Bs[kk][tcol * 8]);
            float4 nb = *reinterpret_cast<const float4*>(&Bs[kk][tcol * 8 + 4]);
            float rm[8] = {ma.x, ma.y, ma.z, ma.w, mb.x, mb.y, mb.z, mb.w};
            float rn[8] = {na.x, na.y, na.z, na.w, nb.x, nb.y, nb.z, nb.w};
#pragma unroll
            for (int i = 0; i < 8; i++)
#pragma unroll
                for (int j = 0; j < 8; j++) acc[i][j] += rm[i] * rn[j];
        }
        __syncthreads();
    }

#pragma unroll
    for (int i = 0; i < 8; i++) {
        int r = trow * 8 + i;
        int tok = stok[r];
        if (tok < 0) continue;
        float p = sprob[r];
        float* yr = y + (size_t)tok * DIM + n0 + tcol * 8;
#pragma unroll
        for (int j = 0; j < 8; j++)
            atomicAdd(yr + j, p * acc[i][j]);
    }
}

// ---------------- launch ------------------------------------------------------
extern "C" void kernel_launch(void* const* d_in, const int* in_sizes, int n_in,
                              void* d_out, int out_size) {
    const float* x     = (const float*)d_in[0];
    const float* Wr    = (const float*)d_in[1];
    const float* br    = (const float*)d_in[2];
    const float* W_in  = (const float*)d_in[3];
    const float* b_in  = (const float*)d_in[4];
    const float* W_out = (const float*)d_in[5];
    const float* b_out = (const float*)d_in[6];
    float* y = (float*)d_out;

    init_kernel<<<1024, 256>>>();
    router_kernel<<<NTOK, 128>>>(x, Wr, br);
    yinit_kernel<<<(NTOK * DIM + 255) / 256, 256>>>(b_out, y);

    dim3 g1(FDIM / BN, NTOK / BM, NEXP);
    gemm1_kernel<<<g1, 256>>>(x, W_in, b_in);

    dim3 g2(DIM / BN, NTOK / BM, NEXP);
    gemm2_kernel<<<g2, 256>>>(W_out, y);
}

// round 15
// speedup vs baseline: 2.4301x; 2.4301x over previous
#include <cuda_runtime.h>
#include <cuda_fp16.h>
#include <cstdint>

// Fixed shapes: B=4, S=1024 -> NTOK=4096, D=1024, F=4096, E=8, TOPK=2
#define NTOK 4096
#define DIM  1024
#define FDIM 4096
#define NEXP 8
#define NCHUNK 8
#define FCH (FDIM / NCHUNK)       // 512 F-columns per slice

#define BM 128
#define BN 64
#define BKC 32                    // K elems per chunk
#define AROW 80                   // padded A row stride in smem (64B data + 16B pad)

// ---------------- device scratch (~4.5 MiB total) -------------------------------
__device__ int   g_count[NEXP];
__device__ int   g_list[NEXP * NTOK];   // entry = token*2 + slot
__device__ float g_prob[NEXP * NTOK];
__device__ int   g_top_e[NTOK * 2];
__device__ float g_top_p[NTOK * 2];
__device__ __align__(256) __half g_h[(size_t)NTOK * FCH];   // 4 MiB fp16 h-slice

// ---------------- helpers -------------------------------------------------------
__device__ __forceinline__ uint32_t s2u(const void* p) {
    uint32_t a;
    asm("{ .reg .u64 t; cvta.to.shared.u64 t, %1; cvt.u32.u64 %0, t; }" : "=r"(a) : "l"(p));
    return a;
}
__device__ __forceinline__ void ldm4(uint32_t& r0, uint32_t& r1, uint32_t& r2, uint32_t& r3,
                                     uint32_t addr) {
    asm volatile("ldmatrix.sync.aligned.m8n8.x4.shared.b16 {%0,%1,%2,%3}, [%4];"
                 : "=r"(r0), "=r"(r1), "=r"(r2), "=r"(r3) : "r"(addr));
}
__device__ __forceinline__ void ldm2t(uint32_t& r0, uint32_t& r1, uint32_t addr) {
    asm volatile("ldmatrix.sync.aligned.m8n8.x2.trans.shared.b16 {%0,%1}, [%2];"
                 : "=r"(r0), "=r"(r1) : "r"(addr));
}
__device__ __forceinline__ void mmaf16(float& c0, float& c1, float& c2, float& c3,
                                       uint32_t a0, uint32_t a1, uint32_t a2, uint32_t a3,
                                       uint32_t b0, uint32_t b1) {
    asm volatile("mma.sync.aligned.m16n8k16.row.col.f32.f16.f16.f32 "
                 "{%0,%1,%2,%3}, {%4,%5,%6,%7}, {%8,%9}, {%0,%1,%2,%3};"
                 : "+f"(c0), "+f"(c1), "+f"(c2), "+f"(c3)
                 : "r"(a0), "r"(a1), "r"(a2), "r"(a3), "r"(b0), "r"(b1));
}
// split 2 fp32 -> (hi f16x2, lo f16x2), pure value ops
__device__ __forceinline__ void split2h(float v0, float v1, uint32_t& hi, uint32_t& lo) {
    __half h0 = __float2half_rn(v0);
    __half h1 = __float2half_rn(v1);
    __half l0 = __float2half_rn(v0 - __half2float(h0));
    __half l1 = __float2half_rn(v1 - __half2float(h1));
    hi = (uint32_t)__half_as_ushort(h0) | ((uint32_t)__half_as_ushort(h1) << 16);
    lo = (uint32_t)__half_as_ushort(l0) | ((uint32_t)__half_as_ushort(l1) << 16);
}
__device__ __forceinline__ void sts8(uint32_t addr, uint32_t a, uint32_t b) {
    asm volatile("st.shared.v2.b32 [%0], {%1,%2};" :: "r"(addr), "r"(a), "r"(b) : "memory");
}

// ---------------- tiny init + h-slice zero --------------------------------------
__global__ void zero_meta_kernel() {
    if (threadIdx.x < NEXP) g_count[threadIdx.x] = 0;
}
__global__ void zero_h_kernel() {
    int i = blockIdx.x * 256 + threadIdx.x;          // 262144 uint4 = 4 MiB
    reinterpret_cast<uint4*>(g_h)[i] = make_uint4(0u, 0u, 0u, 0u);
}

// ---------------- router --------------------------------------------------------
__global__ void router_kernel(const float* __restrict__ x,
                              const float* __restrict__ Wr,
                              const float* __restrict__ br) {
    int n = blockIdx.x;
    int t = threadIdx.x;  // 128
    const float* xr = x + (size_t)n * DIM;
    float acc[NEXP];
#pragma unroll
    for (int e = 0; e < NEXP; e++) acc[e] = 0.f;
    for (int d = t; d < DIM; d += 128) {
        float xv = xr[d];
        const float* w = Wr + (size_t)d * NEXP;
#pragma unroll
        for (int e = 0; e < NEXP; e++) acc[e] += xv * w[e];
    }
#pragma unroll
    for (int e = 0; e < NEXP; e++)
#pragma unroll
        for (int off = 16; off > 0; off >>= 1)
            acc[e] += __shfl_down_sync(0xffffffffu, acc[e], off);
    __shared__ float part[4][NEXP];
    int warp = t >> 5, lane = t & 31;
    if (lane == 0)
#pragma unroll
        for (int e = 0; e < NEXP; e++) part[warp][e] = acc[e];
    __syncthreads();
    if (t == 0) {
        float logit[NEXP], mx = -1e30f;
#pragma unroll
        for (int e = 0; e < NEXP; e++) {
            logit[e] = part[0][e] + part[1][e] + part[2][e] + part[3][e] + br[e];
            mx = fmaxf(mx, logit[e]);
        }
        float p[NEXP], sum = 0.f;
#pragma unroll
        for (int e = 0; e < NEXP; e++) { p[e] = expf(logit[e] - mx); sum += p[e]; }
        float inv = 1.f / sum;
#pragma unroll
        for (int e = 0; e < NEXP; e++) p[e] *= inv;
        int e1 = 0;
#pragma unroll
        for (int e = 1; e < NEXP; e++) if (p[e] > p[e1]) e1 = e;
        int e2 = (e1 == 0) ? 1 : 0;
#pragma unroll
        for (int e = 0; e < NEXP; e++) {
            if (e == e1 || e == e2) continue;
            if (p[e] > p[e2]) e2 = e;
        }
        g_top_e[2 * n] = e1;      g_top_p[2 * n] = p[e1];
        g_top_e[2 * n + 1] = e2;  g_top_p[2 * n + 1] = p[e2];
        int pos1 = atomicAdd(&g_count[e1], 1);
        g_list[e1 * NTOK + pos1] = 2 * n;       g_prob[e1 * NTOK + pos1] = p[e1];
        int pos2 = atomicAdd(&g_count[e2], 1);
        g_list[e2 * NTOK + pos2] = 2 * n + 1;   g_prob[e2 * NTOK + pos2] = p[e2];
    }
}

// ---------------- y init --------------------------------------------------------
__global__ void yinit_kernel(const float* __restrict__ b_out, float* __restrict__ y) {
    size_t i = (size_t)blockIdx.x * blockDim.x + threadIdx.x;  // NTOK*DIM/4
    size_t base = i * 4;
    size_t t = base >> 10;
    size_t d = base & (DIM - 1);
    int e1 = g_top_e[2 * t], e2 = g_top_e[2 * t + 1];
    float p1 = g_top_p[2 * t], p2 = g_top_p[2 * t + 1];
    float4 o1 = *reinterpret_cast<const float4*>(b_out + (size_t)e1 * DIM + d);
    float4 o2 = *reinterpret_cast<const float4*>(b_out + (size_t)e2 * DIM + d);
    float4 r;
    r.x = p1 * o1.x + p2 * o2.x;
    r.y = p1 * o1.y + p2 * o2.y;
    r.z = p1 * o1.z + p2 * o2.z;
    r.w = p1 * o1.w + p2 * o2.w;
    *reinterpret_cast<float4*>(y + base) = r;
}

// ---------------- GEMM1: h_slice += relu(gather(x) @ W_in[:,slice] + b) ---------
// fp32 inputs, reg-staged fp16 hi/lo splits, 3 passes, fp16x2 atomic output.
__global__ void __launch_bounds__(256)
gemm1_kernel(const float* __restrict__ A, const float* __restrict__ Win,
             const float* __restrict__ bias_all, int fc0)
{
    __shared__ int   s_entry[BM];
    __shared__ float s_bias[BN];
    __shared__ __align__(16) char s_ahi[BM * AROW];   // 10240
    __shared__ __align__(16) char s_alo[BM * AROW];   // 10240
    __shared__ __align__(16) char s_bhi[BKC * 128];   // 4096
    __shared__ __align__(16) char s_blo[BKC * 128];   // 4096

    const int e = blockIdx.z;
    const int cnt = g_count[e];
    const int m0 = blockIdx.x * BM;
    if (m0 >= cnt) return;
    const int n0l = blockIdx.y * BN;            // within slice
    const int tid = threadIdx.x;
    const int lane = tid & 31, wid = tid >> 5;
    const int wm = wid >> 1, wn = wid & 1;      // warp tile 32x32

    const uint32_t uahi = s2u(s_ahi), ualo = s2u(s_alo);
    const uint32_t ubhi = s2u(s_bhi), ublo = s2u(s_blo);

    if (tid < BM) {
        int r = m0 + tid;
        s_entry[tid] = (r < cnt) ? g_list[e * NTOK + r] : -1;
    }
    if (tid < BN) s_bias[tid] = bias_all[(size_t)e * FDIM + fc0 + n0l + tid];
    __syncthreads();

    const float* Bp = Win + (size_t)e * DIM * FDIM + fc0 + n0l;

    const int arow0 = tid >> 3;          // +32 strides; 4 float4 per thread (A)
    const int af4   = tid & 7;
    const int brow0 = tid >> 4;          // +16;  2 float4 per thread (B)
    const int bf4   = tid & 15;

    const int sub = lane >> 3, l7 = lane & 7;
    const int mrow0 = wm * 32 + l7 + ((sub & 1) << 3);
    const uint32_t aB0 = uahi + mrow0 * AROW;
    const uint32_t aB1 = uahi + (mrow0 + 16) * AROW;
    const uint32_t aOffLo = ualo - uahi;
    const uint32_t aColSub = (uint32_t)((sub >> 1) << 4);
    const int krl = lane & 15;
    const uint32_t bColBase = (uint32_t)(wn * 64);

    float acc[2][4][4];
#pragma unroll
    for (int mi = 0; mi < 2; mi++)
#pragma unroll
        for (int ni = 0; ni < 4; ni++)
#pragma unroll
            for (int j = 0; j < 4; j++) acc[mi][ni][j] = 0.f;

    const int NK = DIM / BKC;           // 32

    float4 av0, av1, av2, av3, bv0, bv1;
    {
        const float4 z = make_float4(0.f, 0.f, 0.f, 0.f);
        int e0 = s_entry[arow0],      e1_ = s_entry[arow0 + 32];
        int e2_ = s_entry[arow0 + 64], e3 = s_entry[arow0 + 96];
        av0 = (e0 >= 0)  ? *reinterpret_cast<const float4*>(A + (size_t)(e0 >> 1) * DIM + af4 * 4) : z;
        av1 = (e1_ >= 0) ? *reinterpret_cast<const float4*>(A + (size_t)(e1_ >> 1) * DIM + af4 * 4) : z;
        av2 = (e2_ >= 0) ? *reinterpret_cast<const float4*>(A + (size_t)(e2_ >> 1) * DIM + af4 * 4) : z;
        av3 = (e3 >= 0)  ? *reinterpret_cast<const float4*>(A + (size_t)(e3 >> 1) * DIM + af4 * 4) : z;
        bv0 = *reinterpret_cast<const float4*>(Bp + (size_t)brow0 * FDIM + bf4 * 4);
        bv1 = *reinterpret_cast<const float4*>(Bp + (size_t)(brow0 + 16) * FDIM + bf4 * 4);
    }

    for (int kc = 0; kc < NK; kc++) {
        {
            uint32_t h0, l0, h1, l1;
            uint32_t ad = af4 * 8;
            split2h(av0.x, av0.y, h0, l0);  split2h(av0.z, av0.w, h1, l1);
            sts8(uahi + arow0 * AROW + ad, h0, h1);
            sts8(ualo + arow0 * AROW + ad, l0, l1);
            split2h(av1.x, av1.y, h0, l0);  split2h(av1.z, av1.w, h1, l1);
            sts8(uahi + (arow0 + 32) * AROW + ad, h0, h1);
            sts8(ualo + (arow0 + 32) * AROW + ad, l0, l1);
            split2h(av2.x, av2.y, h0, l0);  split2h(av2.z, av2.w, h1, l1);
            sts8(uahi + (arow0 + 64) * AROW + ad, h0, h1);
            sts8(ualo + (arow0 + 64) * AROW + ad, l0, l1);
            split2h(av3.x, av3.y, h0, l0);  split2h(av3.z, av3.w, h1, l1);
            sts8(uahi + (arow0 + 96) * AROW + ad, h0, h1);
            sts8(ualo + (arow0 + 96) * AROW + ad, l0, l1);
            uint32_t sw0 = (uint32_t)(bf4 * 8) ^ ((brow0 & 7) << 4);
            uint32_t sw1 = (uint32_t)(bf4 * 8) ^ (((brow0 + 16) & 7) << 4);
            split2h(bv0.x, bv0.y, h0, l0);  split2h(bv0.z, bv0.w, h1, l1);
            sts8(ubhi + brow0 * 128 + sw0, h0, h1);
            sts8(ublo + brow0 * 128 + sw0, l0, l1);
            split2h(bv1.x, bv1.y, h0, l0);  split2h(bv1.z, bv1.w, h1, l1);
            sts8(ubhi + (brow0 + 16) * 128 + sw1, h0, h1);
            sts8(ublo + (brow0 + 16) * 128 + sw1, l0, l1);
        }
        __syncthreads();

        if (kc + 1 < NK) {
            const float4 z = make_float4(0.f, 0.f, 0.f, 0.f);
            int k0n = (kc + 1) * BKC;
            int e0 = s_entry[arow0],      e1_ = s_entry[arow0 + 32];
            int e2_ = s_entry[arow0 + 64], e3 = s_entry[arow0 + 96];
            av0 = (e0 >= 0)  ? *reinterpret_cast<const float4*>(A + (size_t)(e0 >> 1) * DIM + k0n + af4 * 4) : z;
            av1 = (e1_ >= 0) ? *reinterpret_cast<const float4*>(A + (size_t)(e1_ >> 1) * DIM + k0n + af4 * 4) : z;
            av2 = (e2_ >= 0) ? *reinterpret_cast<const float4*>(A + (size_t)(e2_ >> 1) * DIM + k0n + af4 * 4) : z;
            av3 = (e3 >= 0)  ? *reinterpret_cast<const float4*>(A + (size_t)(e3 >> 1) * DIM + k0n + af4 * 4) : z;
            bv0 = *reinterpret_cast<const float4*>(Bp + (size_t)(k0n + brow0) * FDIM + bf4 * 4);
            bv1 = *reinterpret_cast<const float4*>(Bp + (size_t)(k0n + brow0 + 16) * FDIM + bf4 * 4);
        }

#pragma unroll
        for (int kk = 0; kk < 2; kk++) {
            uint32_t ah[2][4], al[2][4], bh[4][2], bl[4][2];
            uint32_t aCol = (uint32_t)(kk * 32) + aColSub;
            int krow = kk * 16 + krl;
            uint32_t bRow = ubhi + krow * 128;
            uint32_t bXor = (uint32_t)((krow & 7) << 4);

            ldm4(ah[0][0], ah[0][1], ah[0][2], ah[0][3], aB0 + aCol);
            ldm4(ah[1][0], ah[1][1], ah[1][2], ah[1][3], aB1 + aCol);
#pragma unroll
            for (int ni = 0; ni < 4; ni++) {
                uint32_t cb = (bColBase + (uint32_t)(ni << 4)) ^ bXor;
                ldm2t(bh[ni][0], bh[ni][1], bRow + cb);
            }
#pragma unroll
            for (int mi = 0; mi < 2; mi++)
#pragma unroll
                for (int ni = 0; ni < 4; ni++)
                    mmaf16(acc[mi][ni][0], acc[mi][ni][1], acc[mi][ni][2], acc[mi][ni][3],
                           ah[mi][0], ah[mi][1], ah[mi][2], ah[mi][3],
                           bh[ni][0], bh[ni][1]);
#pragma unroll
            for (int ni = 0; ni < 4; ni++) {
                uint32_t cb = (bColBase + (uint32_t)(ni << 4)) ^ bXor;
                ldm2t(bl[ni][0], bl[ni][1], bRow + (ublo - ubhi) + cb);
            }
#pragma unroll
            for (int mi = 0; mi < 2; mi++)
#pragma unroll
                for (int ni = 0; ni < 4; ni++)
                    mmaf16(acc[mi][ni][0], acc[mi][ni][1], acc[mi][ni][2], acc[mi][ni][3],
                           ah[mi][0], ah[mi][1], ah[mi][2], ah[mi][3],
                           bl[ni][0], bl[ni][1]);
            ldm4(al[0][0], al[0][1], al[0][2], al[0][3], aB0 + aOffLo + aCol);
            ldm4(al[1][0], al[1][1], al[1][2], al[1][3], aB1 + aOffLo + aCol);
#pragma unroll
            for (int mi = 0; mi < 2; mi++)
#pragma unroll
                for (int ni = 0; ni < 4; ni++)
                    mmaf16(acc[mi][ni][0], acc[mi][ni][1], acc[mi][ni][2], acc[mi][ni][3],
                           al[mi][0], al[mi][1], al[mi][2], al[mi][3],
                           bh[ni][0], bh[ni][1]);
        }
        __syncthreads();
    }

    // epilogue: relu(acc+bias) -> fp16x2 atomicAdd into h slice
    int g = lane >> 2, t2 = (lane & 3) * 2;
#pragma unroll
    for (int mi = 0; mi < 2; mi++) {
        int r0 = wm * 32 + mi * 16 + g;
        int r1 = r0 + 8;
        int en0 = s_entry[r0], en1 = s_entry[r1];
#pragma unroll
        for (int ni = 0; ni < 4; ni++) {
            int col = wn * 32 + ni * 8 + t2;
            if (en0 >= 0) {
                __half2* o = reinterpret_cast<__half2*>(
                    g_h + (size_t)(en0 >> 1) * FCH + n0l + col);
                atomicAdd(o, __floats2half2_rn(
                    fmaxf(acc[mi][ni][0] + s_bias[col], 0.f),
                    fmaxf(acc[mi][ni][1] + s_bias[col + 1], 0.f)));
            }
            if (en1 >= 0) {
                __half2* o = reinterpret_cast<__half2*>(
                    g_h + (size_t)(en1 >> 1) * FCH + n0l + col);
                atomicAdd(o, __floats2half2_rn(
                    fmaxf(acc[mi][ni][2] + s_bias[col], 0.f),
                    fmaxf(acc[mi][ni][3] + s_bias[col + 1], 0.f)));
            }
        }
    }
}

// ---------------- GEMM2: y += p * (gather(h_slice) @ W_out[slice,:]) ------------
// A fp16 exact (no split), B fp32 -> fp16 hi/lo, 2 passes.
__global__ void __launch_bounds__(256)
gemm2_kernel(const float* __restrict__ Wout, float* __restrict__ y, int fc0)
{
    __shared__ int   s_entry[BM];
    __shared__ float s_prob[BM];
    __shared__ __align__(16) char s_a[BM * AROW];     // 10240 (fp16 exact)
    __shared__ __align__(16) char s_bhi[BKC * 128];   // 4096
    __shared__ __align__(16) char s_blo[BKC * 128];   // 4096

    const int e = blockIdx.z;
    const int cnt = g_count[e];
    const int m0 = blockIdx.x * BM;
    if (m0 >= cnt) return;
    const int n0 = blockIdx.y * BN;
    const int tid = threadIdx.x;
    const int lane = tid & 31, wid = tid >> 5;
    const int wm = wid >> 1, wn = wid & 1;

    const uint32_t usa = s2u(s_a);
    const uint32_t ubhi = s2u(s_bhi), ublo = s2u(s_blo);

    if (tid < BM) {
        int r = m0 + tid;
        s_entry[tid] = (r < cnt) ? g_list[e * NTOK + r] : -1;
        s_prob[tid] = (r < cnt) ? g_prob[e * NTOK + r] : 0.f;
    }
    __syncthreads();

    const float* Bp = Wout + (size_t)e * FDIM * DIM + (size_t)fc0 * DIM + n0;

    // A: 128 rows x 32 halfs (64B) = 512 x 16B; 2 per thread
    const int arow0 = tid >> 2;          // 0..63, +64
    const int af4   = tid & 3;
    const int brow0 = tid >> 4;
    const int bf4   = tid & 15;

    const int sub = lane >> 3, l7 = lane & 7;
    const int mrow0 = wm * 32 + l7 + ((sub & 1) << 3);
    const uint32_t aB0 = usa + mrow0 * AROW;
    const uint32_t aB1 = usa + (mrow0 + 16) * AROW;
    const uint32_t aColSub = (uint32_t)((sub >> 1) << 4);
    const int krl = lane & 15;
    const uint32_t bColBase = (uint32_t)(wn * 64);

    float acc[2][4][4];
#pragma unroll
    for (int mi = 0; mi < 2; mi++)
#pragma unroll
        for (int ni = 0; ni < 4; ni++)
#pragma unroll
            for (int j = 0; j < 4; j++) acc[mi][ni][j] = 0.f;

    const int NK = FCH / BKC;            // 16

    uint4 av0, av1;
    float4 bv0, bv1;
    {
        const uint4 zu = make_uint4(0u, 0u, 0u, 0u);
        int e0 = s_entry[arow0], e1_ = s_entry[arow0 + 64];
        av0 = (e0 >= 0)  ? *reinterpret_cast<const uint4*>(g_h + (size_t)(e0 >> 1) * FCH + af4 * 8) : zu;
        av1 = (e1_ >= 0) ? *reinterpret_cast<const uint4*>(g_h + (size_t)(e1_ >> 1) * FCH + af4 * 8) : zu;
        bv0 = *reinterpret_cast<const float4*>(Bp + (size_t)brow0 * DIM + bf4 * 4);
        bv1 = *reinterpret_cast<const float4*>(Bp + (size_t)(brow0 + 16) * DIM + bf4 * 4);
    }

    for (int kc = 0; kc < NK; kc++) {
        {
            *reinterpret_cast<uint4*>(s_a + arow0 * AROW + af4 * 16) = av0;
            *reinterpret_cast<uint4*>(s_a + (arow0 + 64) * AROW + af4 * 16) = av1;
            uint32_t h0, l0, h1, l1;
            uint32_t sw0 = (uint32_t)(bf4 * 8) ^ ((brow0 & 7) << 4);
            uint32_t sw1 = (uint32_t)(bf4 * 8) ^ (((brow0 + 16) & 7) << 4);
            split2h(bv0.x, bv0.y, h0, l0);  split2h(bv0.z, bv0.w, h1, l1);
            sts8(ubhi + brow0 * 128 + sw0, h0, h1);
            sts8(ublo + brow0 * 128 + sw0, l0, l1);
            split2h(bv1.x, bv1.y, h0, l0);  split2h(bv1.z, bv1.w, h1, l1);
            sts8(ubhi + (brow0 + 16) * 128 + sw1, h0, h1);
            sts8(ublo + (brow0 + 16) * 128 + sw1, l0, l1);
        }
        __syncthreads();

        if (kc + 1 < NK) {
            const uint4 zu = make_uint4(0u, 0u, 0u, 0u);
            int k0n = (kc + 1) * BKC;
            int e0 = s_entry[arow0], e1_ = s_entry[arow0 + 64];
            av0 = (e0 >= 0)  ? *reinterpret_cast<const uint4*>(g_h + (size_t)(e0 >> 1) * FCH + k0n + af4 * 8) : zu;
            av1 = (e1_ >= 0) ? *reinterpret_cast<const uint4*>(g_h + (size_t)(e1_ >> 1) * FCH + k0n + af4 * 8) : zu;
            bv0 = *reinterpret_cast<const float4*>(Bp + (size_t)(k0n + brow0) * DIM + bf4 * 4);
            bv1 = *reinterpret_cast<const float4*>(Bp + (size_t)(k0n + brow0 + 16) * DIM + bf4 * 4);
        }

#pragma unroll
        for (int kk = 0; kk < 2; kk++) {
            uint32_t ah[2][4], bh[4][2], bl[4][2];
            uint32_t aCol = (uint32_t)(kk * 32) + aColSub;
            int krow = kk * 16 + krl;
            uint32_t bRow = ubhi + krow * 128;
            uint32_t bXor = (uint32_t)((krow & 7) << 4);

            ldm4(ah[0][0], ah[0][1], ah[0][2], ah[0][3], aB0 + aCol);
            ldm4(ah[1][0], ah[1][1], ah[1][2], ah[1][3], aB1 + aCol);
#pragma unroll
            for (int ni = 0; ni < 4; ni++) {
                uint32_t cb = (bColBase + (uint32_t)(ni << 4)) ^ bXor;
                ldm2t(bh[ni][0], bh[ni][1], bRow + cb);
                ldm2t(bl[ni][0], bl[ni][1], bRow + (ublo - ubhi) + cb);
            }
#pragma unroll
            for (int mi = 0; mi < 2; mi++)
#pragma unroll
                for (int ni = 0; ni < 4; ni++) {
                    mmaf16(acc[mi][ni][0], acc[mi][ni][1], acc[mi][ni][2], acc[mi][ni][3],
                           ah[mi][0], ah[mi][1], ah[mi][2], ah[mi][3],
                           bh[ni][0], bh[ni][1]);
                    mmaf16(acc[mi][ni][0], acc[mi][ni][1], acc[mi][ni][2], acc[mi][ni][3],
                           ah[mi][0], ah[mi][1], ah[mi][2], ah[mi][3],
                           bl[ni][0], bl[ni][1]);
                }
        }
        __syncthreads();
    }

    // epilogue: y += p * acc
    int g = lane >> 2, t2 = (lane & 3) * 2;
#pragma unroll
    for (int mi = 0; mi < 2; mi++) {
        int r0 = wm * 32 + mi * 16 + g;
        int r1 = r0 + 8;
        int en0 = s_entry[r0], en1 = s_entry[r1];
#pragma unroll
        for (int ni = 0; ni < 4; ni++) {
            int col = wn * 32 + ni * 8 + t2;
            if (en0 >= 0) {
                float p = s_prob[r0];
                float* o = y + (size_t)(en0 >> 1) * DIM + n0 + col;
                atomicAdd(o,     p * acc[mi][ni][0]);
                atomicAdd(o + 1, p * acc[mi][ni][1]);
            }
            if (en1 >= 0) {
                float p = s_prob[r1];
                float* o = y + (size_t)(en1 >> 1) * DIM + n0 + col;
                atomicAdd(o,     p * acc[mi][ni][2]);
                atomicAdd(o + 1, p * acc[mi][ni][3]);
            }
        }
    }
}

// ---------------- launch --------------------------------------------------------
extern "C" void kernel_launch(void* const* d_in, const int* in_sizes, int n_in,
                              void* d_out, int out_size) {
    const float* x     = (const float*)d_in[0];
    const float* Wr    = (const float*)d_in[1];
    const float* br    = (const float*)d_in[2];
    const float* W_in  = (const float*)d_in[3];
    const float* b_in  = (const float*)d_in[4];
    const float* W_out = (const float*)d_in[5];
    const float* b_out = (const float*)d_in[6];
    float* y = (float*)d_out;

    zero_meta_kernel<<<1, 32>>>();
    router_kernel<<<NTOK, 128>>>(x, Wr, br);
    yinit_kernel<<<NTOK * DIM / 4 / 256, 256>>>(b_out, y);

    for (int ch = 0; ch < NCHUNK; ch++) {
        int fc0 = ch * FCH;
        zero_h_kernel<<<NTOK * FCH / 8 / 256, 256>>>();
        dim3 g1(NTOK / BM, FCH / BN, NEXP);
        gemm1_kernel<<<g1, 256>>>(x, W_in, b_in, fc0);
        dim3 g2(NTOK / BM, DIM / BN, NEXP);
        gemm2_kernel<<<g2, 256>>>(W_out, y, fc0);
    }
}